// round 6
// baseline (speedup 1.0000x reference)
#include <cuda_runtime.h>
#include <cuda_bf16.h>
#include <mma.h>
#include <cstdint>

using namespace nvcuda;

#define NB 64
#define NN 1024
#define ND 128
#define THRESH 0.15f      // 0.5 - MARGIN(0.35)
#define TM 128
#define TN 128
#define LDSE 136          // smem leading dim in bf16 elems (272B rows)
#define ROWB (LDSE * 2)
#define TILE_BYTES (TM * ROWB)       // 34816
#define SMEM_DYN (2 * TILE_BYTES)    // A + B single buffer = 69632
#define NCTA2 296                    // 2 CTAs per SM, all resident
#define NSLOTS (NB * 8 * 8)          // 4096 (b, ti, tj) slots

// Scratch (device globals; no allocation allowed)
__device__ __nv_bfloat16 g_P[(size_t)NB * NN * ND];
__device__ __nv_bfloat16 g_Q[(size_t)NB * NN * ND];
__device__ unsigned short g_dest[NB * NN];
__device__ int   g_npos[NB];
__device__ int   g_nneg[NB];
__device__ float g_bsum[NB];
__device__ unsigned int g_done;
__device__ unsigned int g_bar_count;   // zero-init; self-resetting
__device__ unsigned int g_bar_gen;     // monotonic across replays

__device__ __forceinline__ uint32_t smem_u32(const void* p) {
    uint32_t a;
    asm("{ .reg .u64 t; cvta.to.shared.u64 t, %1; cvt.u32.u64 %0, t; }" : "=r"(a) : "l"(p));
    return a;
}
__device__ __forceinline__ void cp16(uint32_t dst, const void* src) {
    asm volatile("cp.async.cg.shared.global [%0], [%1], 16;" :: "r"(dst), "l"(src));
}
#define CP_COMMIT() asm volatile("cp.async.commit_group;" ::: "memory")
#define CP_WAIT0()  asm volatile("cp.async.wait_group 0;" ::: "memory")

// grid-wide barrier: safe because all NCTA2 CTAs are co-resident by construction
__device__ __forceinline__ void grid_barrier() {
    __syncthreads();
    if (threadIdx.x == 0) {
        __threadfence();                       // publish this CTA's writes
        unsigned gen = *(volatile unsigned*)&g_bar_gen;
        if (atomicAdd(&g_bar_count, 1u) == NCTA2 - 1) {
            g_bar_count = 0;
            __threadfence();
            *(volatile unsigned*)&g_bar_gen = gen + 1;
        } else {
            while (*(volatile unsigned*)&g_bar_gen == gen) { }
        }
        __threadfence();                       // acquire others' writes
    }
    __syncthreads();
}

// ---------------------------------------------------------------------------
// THE kernel: scan -> normalize -> GEMM -> finalize, one launch
// grid = 296, block = 256, occ = 2
// ---------------------------------------------------------------------------
__global__ void __launch_bounds__(256, 2)
fused_kernel(const float* __restrict__ emb,
             const int*   __restrict__ labels,
             float* __restrict__ out)
{
    extern __shared__ __align__(16) char smem[];
    const uint32_t smem_base = smem_u32(smem);
    const int tid  = threadIdx.x;
    const int warp = tid >> 5;
    const int lane = tid & 31;

    __shared__ int   s_wtot[8];
    __shared__ float s_w[8];
    __shared__ unsigned int s_rank;

    // ============== Phase 0: scan (CTAs 0..63, one batch each) ==============
    if (blockIdx.x < NB) {
        const int b = blockIdx.x;
        // 256 threads x 4 labels each
        int4 l4 = reinterpret_cast<const int4*>(labels + b * NN)[tid];
        int p0 = (l4.x == 1), p1 = (l4.y == 1), p2 = (l4.z == 1), p3 = (l4.w == 1);
        int tsum = p0 + p1 + p2 + p3;

        int incl = tsum;
#pragma unroll
        for (int o = 1; o < 32; o <<= 1) {
            int v = __shfl_up_sync(0xFFFFFFFFu, incl, o);
            if (lane >= o) incl += v;
        }
        if (lane == 31) s_wtot[warp] = incl;
        __syncthreads();
        if (tid < 8) {
            int v = s_wtot[tid];
#pragma unroll
            for (int o = 1; o < 8; o <<= 1) {
                int u = __shfl_up_sync(0x000000FFu, v, o);
                if (lane >= o) v += u;
            }
            s_wtot[tid] = v;
        }
        __syncthreads();

        int ex = (warp > 0 ? s_wtot[warp - 1] : 0) + incl - tsum;
        int base4 = tid * 4;
        int pp[4] = {p0, p1, p2, p3};
        int run = ex;
#pragma unroll
        for (int j = 0; j < 4; j++) {
            int idx = base4 + j;
            int rank = pp[j] ? run : (idx - run);
            g_dest[b * NN + idx] = (unsigned short)(rank | (pp[j] << 15));
            run += pp[j];
        }

        const int npos = s_wtot[7];
        const int nneg = NN - npos;
        if (tid == 0) {
            g_npos[b] = npos; g_nneg[b] = nneg; g_bsum[b] = 0.0f;
            if (b == 0) g_done = 0u;
        }

        // zero-pad tails to 128-row granularity
        const uint4 z4 = make_uint4(0u, 0u, 0u, 0u);
        int pad_pos = min(NN, ((npos + TM - 1) / TM) * TM);
        int pad_neg = min(NN, ((nneg + TN - 1) / TN) * TN);
        int nzp = (pad_pos - npos) * 16;
        for (int i = tid; i < nzp; i += 256) {
            int r = npos + (i >> 4), c = i & 15;
            reinterpret_cast<uint4*>(g_P + ((size_t)b * NN + r) * ND)[c] = z4;
        }
        int nzn = (pad_neg - nneg) * 16;
        for (int i = tid; i < nzn; i += 256) {
            int r = nneg + (i >> 4), c = i & 15;
            reinterpret_cast<uint4*>(g_Q + ((size_t)b * NN + r) * ND)[c] = z4;
        }
    }

    grid_barrier();

    // ============== Phase 1: normalize + scatter (warp per row) ==============
    {
        const int gw = blockIdx.x * 8 + warp;          // 0..2367
        for (int row = gw; row < NB * NN; row += NCTA2 * 8) {
            const int b = row >> 10, r = row & 1023;
            const float* src = emb + ((size_t)b * NN + r) * ND;
            float v[4];
            float ss = 0.0f;
#pragma unroll
            for (int i = 0; i < 4; i++) { v[i] = src[lane + 32 * i]; ss += v[i] * v[i]; }
#pragma unroll
            for (int o = 16; o > 0; o >>= 1) ss += __shfl_xor_sync(0xFFFFFFFFu, ss, o);
            float inv = 1.0f / fmaxf(sqrtf(ss), 1e-12f);

            unsigned short d = g_dest[b * NN + r];
            int rank  = d & 0x7FFF;
            int ispos = d >> 15;
            __nv_bfloat16* dst = (ispos ? g_P : g_Q) + ((size_t)b * NN + rank) * ND;
#pragma unroll
            for (int i = 0; i < 4; i++) dst[lane + 32 * i] = __float2bfloat16(v[i] * inv);
        }
    }

    grid_barrier();

    // ============== Phase 2: GEMM over valid slots (striped) ==============
    for (int w = blockIdx.x; w < NSLOTS; w += NCTA2) {
        const int b = w >> 6, ti = (w >> 3) & 7, tj = w & 7;
        if (ti * TM >= g_npos[b] || tj * TN >= g_nneg[b]) continue;

        const char* P = (const char*)(g_P + ((size_t)b * NN + ti * TM) * ND);
        const char* Q = (const char*)(g_Q + ((size_t)b * NN + tj * TN) * ND);
        const uint32_t sAa = smem_base;
        const uint32_t sBa = smem_base + TILE_BYTES;
        for (int t = tid; t < TM * 16; t += 256) {
            int r = t >> 4, c = t & 15;
            cp16(sAa + r * ROWB + c * 16, P + (size_t)r * ND * 2 + c * 16);
            cp16(sBa + r * ROWB + c * 16, Q + (size_t)r * ND * 2 + c * 16);
        }
        CP_COMMIT();
        CP_WAIT0();
        __syncthreads();

        const __nv_bfloat16* sA = (const __nv_bfloat16*)(smem);
        const __nv_bfloat16* sB = (const __nv_bfloat16*)(smem + TILE_BYTES);
        const int wrow = warp >> 1;   // 0..3 -> rows wrow*32
        const int wcol = warp & 1;    // 0..1 -> cols wcol*64

        wmma::fragment<wmma::accumulator, 16, 16, 16, float> acc[2][4];
#pragma unroll
        for (int i = 0; i < 2; i++)
#pragma unroll
            for (int j = 0; j < 4; j++) wmma::fill_fragment(acc[i][j], 0.0f);

#pragma unroll
        for (int k = 0; k < ND; k += 16) {
            wmma::fragment<wmma::matrix_a, 16, 16, 16, __nv_bfloat16, wmma::row_major> a[2];
            wmma::fragment<wmma::matrix_b, 16, 16, 16, __nv_bfloat16, wmma::col_major> bb[4];
#pragma unroll
            for (int i = 0; i < 2; i++)
                wmma::load_matrix_sync(a[i], sA + (wrow * 32 + i * 16) * LDSE + k, LDSE);
#pragma unroll
            for (int j = 0; j < 4; j++)
                wmma::load_matrix_sync(bb[j], sB + (wcol * 64 + j * 16) * LDSE + k, LDSE);
#pragma unroll
            for (int i = 0; i < 2; i++)
#pragma unroll
                for (int j = 0; j < 4; j++)
                    wmma::mma_sync(acc[i][j], a[i], bb[j], acc[i][j]);
        }

        float s = 0.0f;
#pragma unroll
        for (int i = 0; i < 2; i++)
#pragma unroll
            for (int j = 0; j < 4; j++)
#pragma unroll
                for (int e = 0; e < acc[i][j].num_elements; e++)
                    s += fmaxf(acc[i][j].x[e] - THRESH, 0.0f);
#pragma unroll
        for (int o = 16; o > 0; o >>= 1) s += __shfl_xor_sync(0xFFFFFFFFu, s, o);
        if (lane == 0) s_w[warp] = s;
        __syncthreads();
        if (tid == 0) {
            float ts = 0.0f;
#pragma unroll
            for (int i = 0; i < 8; i++) ts += s_w[i];
            atomicAdd(&g_bsum[b], ts);
        }
        __syncthreads();   // smem buffer + s_w free for next slot
    }

    // ============== Finalize: completion ticket ==============
    if (tid == 0) {
        __threadfence();
        s_rank = atomicAdd(&g_done, 1u);
    }
    __syncthreads();
    if (s_rank == NCTA2 - 1 && tid == 0) {
        __threadfence();
        float L = 0.0f, C = 0.0f;
        for (int i = 0; i < NB; i++) {
            int np = g_npos[i], nn = g_nneg[i];
            if (np > 0 && nn > 0) {
                L += g_bsum[i] / (float)nn;
                C += (float)np;
            }
        }
        out[0] = L / fmaxf(C, 1.0f);
    }
}

// ---------------------------------------------------------------------------
extern "C" void kernel_launch(void* const* d_in, const int* in_sizes, int n_in,
                              void* d_out, int out_size)
{
    const float* emb    = (const float*)d_in[0];
    const int*   labels = (const int*)d_in[1];
    float*       out    = (float*)d_out;

    cudaFuncSetAttribute(fused_kernel,
                         cudaFuncAttributeMaxDynamicSharedMemorySize, SMEM_DYN);

    fused_kernel<<<NCTA2, 256, SMEM_DYN>>>(emb, labels, out);
}

// round 7
// speedup vs baseline: 1.7221x; 1.7221x over previous
#include <cuda_runtime.h>
#include <cuda_bf16.h>
#include <mma.h>
#include <cstdint>

using namespace nvcuda;

#define NB 64
#define NN 1024
#define ND 128
#define THRESH 0.15f      // 0.5 - MARGIN(0.35)
#define TM 128
#define TN 128
#define LDSE 136          // smem leading dim in bf16 elems (272B rows)
#define ROWB (LDSE * 2)
#define TILE_BYTES (TM * ROWB)        // 34816
#define SMEM_DYN (3 * TILE_BYTES)     // A + 2x B = 104448 (occ 2: <= 114KB)
#define GEMM_CTAS (8 * NB)            // 512

// Scratch (device globals; no allocation allowed)
__device__ __nv_bfloat16 g_P[(size_t)NB * NN * ND];
__device__ __nv_bfloat16 g_Q[(size_t)NB * NN * ND];
__device__ unsigned short g_dest[NB * NN];
__device__ int   g_npos[NB];
__device__ int   g_nneg[NB];
__device__ float g_bsum[NB];
__device__ unsigned int g_done;

__device__ __forceinline__ uint32_t smem_u32(const void* p) {
    uint32_t a;
    asm("{ .reg .u64 t; cvta.to.shared.u64 t, %1; cvt.u32.u64 %0, t; }" : "=r"(a) : "l"(p));
    return a;
}
__device__ __forceinline__ void cp16(uint32_t dst, const void* src) {
    asm volatile("cp.async.cg.shared.global [%0], [%1], 16;" :: "r"(dst), "l"(src));
}
#define CP_COMMIT() asm volatile("cp.async.commit_group;" ::: "memory")
#define CP_WAIT(n)  asm volatile("cp.async.wait_group %0;" :: "n"(n) : "memory")

// ---------------------------------------------------------------------------
// Kernel A0: per-batch compaction map via block scan + zero pad rows
// grid = 64, block = 256 (int4 labels, 4 per thread)
// ---------------------------------------------------------------------------
__global__ void __launch_bounds__(256)
scan_kernel(const int* __restrict__ labels)
{
    const int b = blockIdx.x;
    const int tid = threadIdx.x;
    const int warp = tid >> 5, lane = tid & 31;

    __shared__ int s_wtot[8];

    int4 l4 = reinterpret_cast<const int4*>(labels + b * NN)[tid];
    int p0 = (l4.x == 1), p1 = (l4.y == 1), p2 = (l4.z == 1), p3 = (l4.w == 1);
    int tsum = p0 + p1 + p2 + p3;

    int incl = tsum;
#pragma unroll
    for (int o = 1; o < 32; o <<= 1) {
        int v = __shfl_up_sync(0xFFFFFFFFu, incl, o);
        if (lane >= o) incl += v;
    }
    if (lane == 31) s_wtot[warp] = incl;
    __syncthreads();
    if (tid < 8) {
        int v = s_wtot[tid];
#pragma unroll
        for (int o = 1; o < 8; o <<= 1) {
            int u = __shfl_up_sync(0x000000FFu, v, o);
            if (lane >= o) v += u;
        }
        s_wtot[tid] = v;
    }
    __syncthreads();

    int run = (warp > 0 ? s_wtot[warp - 1] : 0) + incl - tsum;
    int base4 = tid * 4;
    int pp[4] = {p0, p1, p2, p3};
#pragma unroll
    for (int j = 0; j < 4; j++) {
        int idx = base4 + j;
        int rank = pp[j] ? run : (idx - run);
        g_dest[b * NN + idx] = (unsigned short)(rank | (pp[j] << 15));
        run += pp[j];
    }

    const int npos = s_wtot[7];
    const int nneg = NN - npos;
    if (tid == 0) {
        g_npos[b] = npos; g_nneg[b] = nneg; g_bsum[b] = 0.0f;
        if (b == 0) g_done = 0u;
    }

    // zero-pad tails to 128-row granularity (GEMM then needs no masking)
    const uint4 z4 = make_uint4(0u, 0u, 0u, 0u);
    int pad_pos = min(NN, ((npos + TM - 1) / TM) * TM);
    int pad_neg = min(NN, ((nneg + TN - 1) / TN) * TN);
    int nzp = (pad_pos - npos) * 16;
    for (int i = tid; i < nzp; i += 256) {
        int r = npos + (i >> 4), c = i & 15;
        reinterpret_cast<uint4*>(g_P + ((size_t)b * NN + r) * ND)[c] = z4;
    }
    int nzn = (pad_neg - nneg) * 16;
    for (int i = tid; i < nzn; i += 256) {
        int r = nneg + (i >> 4), c = i & 15;
        reinterpret_cast<uint4*>(g_Q + ((size_t)b * NN + r) * ND)[c] = z4;
    }
}

// ---------------------------------------------------------------------------
// Kernel A1: normalize + compacted scatter. One warp per row.
// ---------------------------------------------------------------------------
__global__ void __launch_bounds__(256)
normalize_scatter_kernel(const float* __restrict__ emb)
{
    const int b = blockIdx.y;
    const int wid  = threadIdx.x >> 5;
    const int lane = threadIdx.x & 31;
    const int r = blockIdx.x * 8 + wid;

    const float* src = emb + ((size_t)b * NN + r) * ND;
    float v[4];
    float ss = 0.0f;
#pragma unroll
    for (int i = 0; i < 4; i++) { v[i] = src[lane + 32 * i]; ss += v[i] * v[i]; }
#pragma unroll
    for (int o = 16; o > 0; o >>= 1) ss += __shfl_xor_sync(0xFFFFFFFFu, ss, o);
    float inv = 1.0f / fmaxf(sqrtf(ss), 1e-12f);

    unsigned short d = g_dest[b * NN + r];
    int rank  = d & 0x7FFF;
    int ispos = d >> 15;
    __nv_bfloat16* dst = (ispos ? g_P : g_Q) + ((size_t)b * NN + rank) * ND;
#pragma unroll
    for (int i = 0; i < 4; i++) dst[lane + 32 * i] = __float2bfloat16(v[i] * inv);
}

// ---------------------------------------------------------------------------
// Kernel B: A-resident streaming GEMM. CTA = (ti, b); A tile loaded once,
// B tiles double-buffered under compute. grid = (8, 64), 256 threads, occ 2.
// ---------------------------------------------------------------------------
__global__ void __launch_bounds__(256, 2)
hinge_gemm_kernel(float* __restrict__ out)
{
    extern __shared__ __align__(16) char smem[];
    const uint32_t smem_base = smem_u32(smem);
    const int tid  = threadIdx.x;
    const int warp = tid >> 5;
    const int lane = tid & 31;

    const int ti = blockIdx.x;
    const int b  = blockIdx.y;
    const int npos = g_npos[b];
    const int nneg = g_nneg[b];
    const int njt  = (nneg + TN - 1) / TN;     // valid B tiles (padded rows are zero)
    const bool active = (ti * TM < npos) && (njt > 0);

    if (active) {
        const char* P = (const char*)(g_P + ((size_t)b * NN + ti * TM) * ND);
        const char* Qb = (const char*)(g_Q + (size_t)b * NN * ND);
        const uint32_t sAa  = smem_base;
        const uint32_t sB0a = smem_base + TILE_BYTES;

        // load A + first B tile (one group)
        for (int t = tid; t < TM * 16; t += 256) {
            int r = t >> 4, c = t & 15;
            cp16(sAa + r * ROWB + c * 16, P + (size_t)r * ND * 2 + c * 16);
            cp16(sB0a + r * ROWB + c * 16, Qb + (size_t)r * ND * 2 + c * 16);
        }
        CP_COMMIT();

        const __nv_bfloat16* sA = (const __nv_bfloat16*)(smem);
        const int wrow = warp >> 1;   // 0..3 -> rows wrow*32
        const int wcol = warp & 1;    // 0..1 -> cols wcol*64

        // A fragments are loop-invariant per tj; hinge sum accumulated across tiles
        float s = 0.0f;

        for (int tj = 0; tj < njt; tj++) {
            const int cbuf = tj & 1;
            if (tj + 1 < njt) {       // prefetch next B into alternate buffer
                const char* Qn = Qb + (size_t)(tj + 1) * TN * ND * 2;
                uint32_t sBn = smem_base + TILE_BYTES * (1 + ((tj + 1) & 1));
                for (int t = tid; t < TN * 16; t += 256) {
                    int r = t >> 4, c = t & 15;
                    cp16(sBn + r * ROWB + c * 16, Qn + (size_t)r * ND * 2 + c * 16);
                }
                CP_COMMIT();
                CP_WAIT(1);           // current B (and A) complete
            } else {
                CP_WAIT(0);
            }
            __syncthreads();          // all threads' copies visible

            const __nv_bfloat16* sB =
                (const __nv_bfloat16*)(smem + TILE_BYTES * (1 + cbuf));

            wmma::fragment<wmma::accumulator, 16, 16, 16, float> acc[2][4];
#pragma unroll
            for (int i = 0; i < 2; i++)
#pragma unroll
                for (int j = 0; j < 4; j++) wmma::fill_fragment(acc[i][j], 0.0f);

#pragma unroll
            for (int k = 0; k < ND; k += 16) {
                wmma::fragment<wmma::matrix_a, 16, 16, 16, __nv_bfloat16, wmma::row_major> a[2];
                wmma::fragment<wmma::matrix_b, 16, 16, 16, __nv_bfloat16, wmma::col_major> bb[4];
#pragma unroll
                for (int i = 0; i < 2; i++)
                    wmma::load_matrix_sync(a[i], sA + (wrow * 32 + i * 16) * LDSE + k, LDSE);
#pragma unroll
                for (int j = 0; j < 4; j++)
                    wmma::load_matrix_sync(bb[j], sB + (wcol * 64 + j * 16) * LDSE + k, LDSE);
#pragma unroll
                for (int i = 0; i < 2; i++)
#pragma unroll
                    for (int j = 0; j < 4; j++)
                        wmma::mma_sync(acc[i][j], a[i], bb[j], acc[i][j]);
            }

#pragma unroll
            for (int i = 0; i < 2; i++)
#pragma unroll
                for (int j = 0; j < 4; j++)
#pragma unroll
                    for (int e = 0; e < acc[i][j].num_elements; e++)
                        s += fmaxf(acc[i][j].x[e] - THRESH, 0.0f);

            __syncthreads();          // compute done before buffer cbuf is refilled
        }

        // one reduce + one atomic per CTA
#pragma unroll
        for (int o = 16; o > 0; o >>= 1) s += __shfl_xor_sync(0xFFFFFFFFu, s, o);
        __shared__ float s_w[8];
        if (lane == 0) s_w[warp] = s;
        __syncthreads();
        if (tid == 0) {
            float ts = 0.0f;
#pragma unroll
            for (int i = 0; i < 8; i++) ts += s_w[i];
            atomicAdd(&g_bsum[b], ts);
        }
    }

    // completion ticket; last CTA computes the final scalar
    __shared__ unsigned int s_rank;
    if (tid == 0) {
        __threadfence();
        s_rank = atomicAdd(&g_done, 1u);
    }
    __syncthreads();
    if (s_rank == GEMM_CTAS - 1 && tid == 0) {
        __threadfence();
        float L = 0.0f, C = 0.0f;
        for (int i = 0; i < NB; i++) {
            int np = g_npos[i], nn = g_nneg[i];
            if (np > 0 && nn > 0) {
                L += g_bsum[i] / (float)nn;
                C += (float)np;
            }
        }
        out[0] = L / fmaxf(C, 1.0f);
    }
}

// ---------------------------------------------------------------------------
extern "C" void kernel_launch(void* const* d_in, const int* in_sizes, int n_in,
                              void* d_out, int out_size)
{
    const float* emb    = (const float*)d_in[0];
    const int*   labels = (const int*)d_in[1];
    float*       out    = (float*)d_out;

    cudaFuncSetAttribute(hinge_gemm_kernel,
                         cudaFuncAttributeMaxDynamicSharedMemorySize, SMEM_DYN);

    scan_kernel<<<NB, 256>>>(labels);

    dim3 gridA(NN / 8, NB);
    normalize_scatter_kernel<<<gridA, 256>>>(emb);

    dim3 gridB(8, NB);   // (ti, b) = 512 CTAs
    hinge_gemm_kernel<<<gridB, 256, SMEM_DYN>>>(out);
}